// round 1
// baseline (speedup 1.0000x reference)
#include <cuda_runtime.h>
#include <cstdint>

// Problem shapes (fixed by the dataset)
#define BB 16
#define CC 256
#define HH 128
#define WW 128
#define NV 4096
#define DD 256
#define MROWS (BB * NV)   // 65536
#define HWSZ (HH * WW)    // 16384

// Scratch (static __device__ arrays — allocation-free per the rules)
__device__ float g_featT[(size_t)BB * HWSZ * CC];  // 256 MiB: features transposed to (B,H,W,C)
__device__ float g_bufA[(size_t)MROWS * CC];       // 64 MiB: sampled, later reused for vfeat+pos
__device__ float g_bufB[(size_t)MROWS * DD];       // 64 MiB: h = relu(...)

// image_size may arrive as int32 or float32; decode robustly on device.
__device__ __forceinline__ float read_img(const int* p) {
    int iv = *p;
    if (iv > 1 && iv < (1 << 24)) return (float)iv;
    return __int_as_float(iv);
}

// ---------------------------------------------------------------------------
// Kernel 1: transpose (B,C,H,W) -> (B,HW,C) so gathers become coalesced
// ---------------------------------------------------------------------------
__global__ void transpose_kernel(const float* __restrict__ src) {
    __shared__ float tile[32][33];
    int b = blockIdx.z;
    int hw0 = blockIdx.x * 32;
    int c0 = blockIdx.y * 32;
    const float* s = src + (size_t)b * CC * HWSZ;
    float* d = g_featT + (size_t)b * HWSZ * CC;
#pragma unroll
    for (int i = threadIdx.y; i < 32; i += 8)
        tile[i][threadIdx.x] = s[(size_t)(c0 + i) * HWSZ + hw0 + threadIdx.x];
    __syncthreads();
#pragma unroll
    for (int i = threadIdx.y; i < 32; i += 8)
        d[(size_t)(hw0 + i) * CC + c0 + threadIdx.x] = tile[threadIdx.x][i];
}

// ---------------------------------------------------------------------------
// Kernel 2: bilinear gather. One warp per vertex; each lane handles 8 channels
// with LDG.128 (4 corner rows are contiguous runs of 256 channels).
// Matches reference math: align_corners=True, border clamp, two-stage lerp.
// ---------------------------------------------------------------------------
__global__ void gather_kernel(const float* __restrict__ verts,
                              const int* __restrict__ imgp) {
    int v = blockIdx.x * 4 + (threadIdx.x >> 5);
    int lane = threadIdx.x & 31;
    int b = v >> 12;  // /NV

    float img = read_img(imgp);
    float denom = img - 1.0f;
    float vx = verts[2 * v + 0];
    float vy = verts[2 * v + 1];
    float gx = 2.0f * vx / denom - 1.0f;
    float gy = 2.0f * vy / denom - 1.0f;
    float ix = (gx + 1.0f) * 0.5f * (float)(WW - 1);
    float iy = (gy + 1.0f) * 0.5f * (float)(HH - 1);
    ix = fminf(fmaxf(ix, 0.0f), (float)(WW - 1));
    iy = fminf(fmaxf(iy, 0.0f), (float)(HH - 1));
    float x0f = floorf(ix), y0f = floorf(iy);
    float wx = ix - x0f, wy = iy - y0f;
    int x0 = min(max((int)x0f, 0), WW - 1);
    int y0 = min(max((int)y0f, 0), HH - 1);
    int x1 = min(x0 + 1, WW - 1);
    int y1 = min(y0 + 1, HH - 1);

    const float* base = g_featT + (size_t)b * HWSZ * CC;
    const float* p00 = base + (size_t)(y0 * WW + x0) * CC;
    const float* p01 = base + (size_t)(y0 * WW + x1) * CC;
    const float* p10 = base + (size_t)(y1 * WW + x0) * CC;
    const float* p11 = base + (size_t)(y1 * WW + x1) * CC;
    float* out = g_bufA + (size_t)v * CC;

    float omx = 1.0f - wx, omy = 1.0f - wy;
    int c = lane * 8;
#pragma unroll
    for (int q = 0; q < 2; q++, c += 4) {
        float4 a00 = *(const float4*)(p00 + c);
        float4 a01 = *(const float4*)(p01 + c);
        float4 a10 = *(const float4*)(p10 + c);
        float4 a11 = *(const float4*)(p11 + c);
        float4 r;
        {
            float top = a00.x * omx + a01.x * wx;
            float bot = a10.x * omx + a11.x * wx;
            r.x = top * omy + bot * wy;
        }
        {
            float top = a00.y * omx + a01.y * wx;
            float bot = a10.y * omx + a11.y * wx;
            r.y = top * omy + bot * wy;
        }
        {
            float top = a00.z * omx + a01.z * wx;
            float bot = a10.z * omx + a11.z * wx;
            r.z = top * omy + bot * wy;
        }
        {
            float top = a00.w * omx + a01.w * wx;
            float bot = a10.w * omx + a11.w * wx;
            r.w = top * omy + bot * wy;
        }
        *(float4*)(out + c) = r;
    }
}

// ---------------------------------------------------------------------------
// Packed f32x2 helpers (FFMA2 — only reachable via PTX on sm_103a)
// ---------------------------------------------------------------------------
__device__ __forceinline__ unsigned long long pk2(float lo, float hi) {
    unsigned long long r;
    asm("mov.b64 %0, {%1, %2};" : "=l"(r) : "f"(lo), "f"(hi));
    return r;
}
__device__ __forceinline__ void fma2(unsigned long long& d,
                                     unsigned long long a,
                                     unsigned long long b) {
    asm("fma.rn.f32x2 %0, %1, %2, %0;" : "+l"(d) : "l"(a), "l"(b));
}
__device__ __forceinline__ void upk2(unsigned long long v, float& lo, float& hi) {
    asm("mov.b64 {%0, %1}, %2;" : "=f"(lo), "=f"(hi) : "l"(v));
}

// ---------------------------------------------------------------------------
// Kernel 3/4/5: SGEMM with packed-f32x2 inner product.
//   C[M,Nd] = epilogue(A[M,K] @ W[K,Nd] + bias)
// MODE 0: relu        (GEMM1, bias=b1)
// MODE 1: + pos_enc   (GEMM2, bias=b2) — sinusoidal encoding fused in epilogue
// MODE 2: plain       (GEMM3, bias=bp)
// Tile 128x128x16, 256 threads, 8x8 per thread (accumulated as 8x4 f32x2).
// ---------------------------------------------------------------------------
template <int MODE>
__global__ void __launch_bounds__(256, 2)
gemm_kernel(const float* __restrict__ A, const float* __restrict__ Wm,
            const float* __restrict__ bias, float* __restrict__ Cout,
            const float* __restrict__ verts, const int* __restrict__ imgp) {
    constexpr int BM = 128, BN = 128, BK = 16, K = CC, Nd = DD;
    __shared__ float As[BK][BM];
    __shared__ float Bs[BK][BN];

    int tid = threadIdx.x;
    int tm = tid >> 4, tn = tid & 15;
    int brow = blockIdx.y * BM;
    int bcol = blockIdx.x * BN;

    unsigned long long acc[8][4];
#pragma unroll
    for (int i = 0; i < 8; i++)
#pragma unroll
        for (int j = 0; j < 4; j++) acc[i][j] = 0ull;

    const float* Ablk = A + (size_t)brow * K;

    for (int k0 = 0; k0 < K; k0 += BK) {
#pragma unroll
        for (int it = 0; it < 2; it++) {
            int l = tid + it * 256;
            int r = l >> 2;
            int kq = (l & 3) << 2;
            float4 va = *(const float4*)(Ablk + (size_t)r * K + k0 + kq);
            As[kq + 0][r] = va.x;
            As[kq + 1][r] = va.y;
            As[kq + 2][r] = va.z;
            As[kq + 3][r] = va.w;
            int rb = l >> 5;
            int cb = (l & 31) << 2;
            *(float4*)&Bs[rb][cb] =
                *(const float4*)(Wm + (size_t)(k0 + rb) * Nd + bcol + cb);
        }
        __syncthreads();
#pragma unroll
        for (int k = 0; k < BK; k++) {
            float a[8];
            *(float4*)&a[0] = *(const float4*)&As[k][tm * 8];
            *(float4*)&a[4] = *(const float4*)&As[k][tm * 8 + 4];
            unsigned long long bb[4];
#pragma unroll
            for (int j = 0; j < 4; j++)
                bb[j] = *(const unsigned long long*)&Bs[k][tn * 8 + j * 2];
#pragma unroll
            for (int i = 0; i < 8; i++) {
                unsigned long long pa = pk2(a[i], a[i]);
#pragma unroll
                for (int j = 0; j < 4; j++) fma2(acc[i][j], pa, bb[j]);
            }
        }
        __syncthreads();
    }

    // ---- epilogue ----
    int gc0 = bcol + tn * 8;
    float bv[8];
#pragma unroll
    for (int jj = 0; jj < 8; jj++) bv[jj] = bias[gc0 + jj];

    float fr[4];
    float img = 0.0f;
    int coff = 0;
    if (MODE == 1) {
        img = read_img(imgp);
        coff = (gc0 >= 128) ? 1 : 0;  // first 128 cols from x, next 128 from y
        int f0 = (gc0 & 127) >> 1;    // frequency index of first pair
#pragma unroll
        for (int t = 0; t < 4; t++)
            fr[t] = exp2f(-(float)(f0 + t) * 0.20762050593046015f);  // 10000^(-i/64)
    }

#pragma unroll
    for (int i = 0; i < 8; i++) {
        int m = brow + tm * 8 + i;
        float o[8];
#pragma unroll
        for (int j = 0; j < 4; j++) {
            float lo, hi;
            upk2(acc[i][j], lo, hi);
            o[2 * j] = lo + bv[2 * j];
            o[2 * j + 1] = hi + bv[2 * j + 1];
        }
        if (MODE == 0) {
#pragma unroll
            for (int jj = 0; jj < 8; jj++) o[jj] = fmaxf(o[jj], 0.0f);
        }
        if (MODE == 1) {
            float v = verts[2 * m + coff];
            float xx = (v / img) * 1000.0f;
#pragma unroll
            for (int t = 0; t < 4; t++) {
                float ang = xx * fr[t];
                // Cody-Waite reduction mod 2*pi (|ang| <= ~1000), then MUFU sin/cos
                float kk = rintf(ang * 0.15915494309189535f);
                float rr = fmaf(-kk, 6.2831854820251465f, ang);
                rr = fmaf(-kk, -1.7484555e-07f, rr);
                o[2 * t] += __sinf(rr);
                o[2 * t + 1] += __cosf(rr);
            }
        }
        float* cp = Cout + (size_t)m * Nd + gc0;
        *(float4*)cp = make_float4(o[0], o[1], o[2], o[3]);
        *(float4*)(cp + 4) = make_float4(o[4], o[5], o[6], o[7]);
    }
}

// ---------------------------------------------------------------------------
// Launch: transpose -> gather -> GEMM1(relu) -> GEMM2(+posenc) -> GEMM3
// ---------------------------------------------------------------------------
extern "C" void kernel_launch(void* const* d_in, const int* in_sizes, int n_in,
                              void* d_out, int out_size) {
    const float* features = (const float*)d_in[0];
    const float* vertices = (const float*)d_in[1];
    const int* imgp = (const int*)d_in[2];
    const float* W1 = (const float*)d_in[3];
    const float* b1 = (const float*)d_in[4];
    const float* W2 = (const float*)d_in[5];
    const float* b2 = (const float*)d_in[6];
    const float* Wp = (const float*)d_in[7];
    const float* bp = (const float*)d_in[8];
    float* out = (float*)d_out;

    void *pA = nullptr, *pB = nullptr;
    cudaGetSymbolAddress(&pA, g_featT);  // force-resolve module (no-op use)
    cudaGetSymbolAddress(&pA, g_bufA);
    cudaGetSymbolAddress(&pB, g_bufB);
    float* bufA = (float*)pA;
    float* bufB = (float*)pB;

    transpose_kernel<<<dim3(HWSZ / 32, CC / 32, BB), dim3(32, 8)>>>(features);
    gather_kernel<<<MROWS / 4, 128>>>(vertices, imgp);

    dim3 gg(DD / 128, MROWS / 128);
    gemm_kernel<0><<<gg, 256>>>(bufA, W1, b1, bufB, vertices, imgp);
    gemm_kernel<1><<<gg, 256>>>(bufB, W2, b2, bufA, vertices, imgp);
    gemm_kernel<2><<<gg, 256>>>(bufA, Wp, bp, out, vertices, imgp);
}

// round 3
// speedup vs baseline: 1.6802x; 1.6802x over previous
#include <cuda_runtime.h>
#include <cuda_bf16.h>
#include <cstdint>

#define BB 16
#define CC 256
#define HH 128
#define WW 128
#define NV 4096
#define DD 256
#define MROWS (BB * NV)   // 65536
#define HWSZ (HH * WW)    // 16384

// ---------------- scratch (static __device__: allocation-free) ----------------
__device__ float g_featT[(size_t)BB * HWSZ * CC];       // 256 MiB transposed features (B,HW,C)
__device__ __nv_bfloat16 g_Ahi[(size_t)MROWS * CC];     // activations ping (hi)
__device__ __nv_bfloat16 g_Alo[(size_t)MROWS * CC];     // activations ping (lo)
__device__ __nv_bfloat16 g_Chi[(size_t)MROWS * CC];     // activations pong (hi)
__device__ __nv_bfloat16 g_Clo[(size_t)MROWS * CC];     // activations pong (lo)
__device__ __nv_bfloat16 g_Whi[3][DD * CC];             // weights [N,K] K-major, hi
__device__ __nv_bfloat16 g_Wlo[3][DD * CC];             // weights lo

__device__ __forceinline__ float read_img(const int* p) {
    int iv = *p;
    if (iv > 1 && iv < (1 << 24)) return (float)iv;
    return __int_as_float(iv);
}

// ---------------- family-agnostic PTX helpers (sm_80+) ----------------
__device__ __forceinline__ uint32_t smem_u32(const void* p) {
    uint32_t a;
    asm("{ .reg .u64 t; cvta.to.shared.u64 t, %1; cvt.u32.u64 %0, t; }" : "=r"(a) : "l"(p));
    return a;
}
__device__ __forceinline__ void cpa16(uint32_t dst, const void* src) {
    asm volatile("cp.async.cg.shared.global [%0], [%1], 16;" :: "r"(dst), "l"(src));
}
#define CP_COMMIT() asm volatile("cp.async.commit_group;" ::: "memory")
#define CP_WAIT1() asm volatile("cp.async.wait_group 1;" ::: "memory")

__device__ __forceinline__ void ldsm4(uint32_t a, uint32_t& r0, uint32_t& r1,
                                      uint32_t& r2, uint32_t& r3) {
    asm volatile("ldmatrix.sync.aligned.m8n8.x4.shared.b16 {%0,%1,%2,%3}, [%4];"
                 : "=r"(r0), "=r"(r1), "=r"(r2), "=r"(r3) : "r"(a));
}
__device__ __forceinline__ void mma16816(float* c, const uint32_t* a, const uint32_t* b) {
    asm volatile(
        "mma.sync.aligned.m16n8k16.row.col.f32.bf16.bf16.f32 "
        "{%0,%1,%2,%3}, {%4,%5,%6,%7}, {%8,%9}, {%0,%1,%2,%3};"
        : "+f"(c[0]), "+f"(c[1]), "+f"(c[2]), "+f"(c[3])
        : "r"(a[0]), "r"(a[1]), "r"(a[2]), "r"(a[3]), "r"(b[0]), "r"(b[1]));
}

// ---------------------------------------------------------------------------
// K1: transpose (B,C,H,W) -> (B,HW,C) fp32 (keeps bilinear math in fp32)
// ---------------------------------------------------------------------------
__global__ void transpose_kernel(const float* __restrict__ src) {
    __shared__ float tile[32][33];
    int b = blockIdx.z;
    int hw0 = blockIdx.x * 32;
    int c0 = blockIdx.y * 32;
    const float* s = src + (size_t)b * CC * HWSZ;
    float* d = g_featT + (size_t)b * HWSZ * CC;
#pragma unroll
    for (int i = threadIdx.y; i < 32; i += 8)
        tile[i][threadIdx.x] = s[(size_t)(c0 + i) * HWSZ + hw0 + threadIdx.x];
    __syncthreads();
#pragma unroll
    for (int i = threadIdx.y; i < 32; i += 8)
        d[(size_t)(hw0 + i) * CC + c0 + threadIdx.x] = tile[threadIdx.x][i];
}

// ---------------------------------------------------------------------------
// K2: bilinear gather -> hi/lo bf16 split (GEMM1 A operand produced directly)
// ---------------------------------------------------------------------------
__global__ void gather_kernel(const float* __restrict__ verts,
                              const int* __restrict__ imgp,
                              __nv_bfloat16* __restrict__ OAh,
                              __nv_bfloat16* __restrict__ OAl) {
    int v = blockIdx.x * 4 + (threadIdx.x >> 5);
    int lane = threadIdx.x & 31;
    int b = v >> 12;

    float img = read_img(imgp);
    float denom = img - 1.0f;
    float gx = 2.0f * verts[2 * v + 0] / denom - 1.0f;
    float gy = 2.0f * verts[2 * v + 1] / denom - 1.0f;
    float ix = (gx + 1.0f) * 0.5f * (float)(WW - 1);
    float iy = (gy + 1.0f) * 0.5f * (float)(HH - 1);
    ix = fminf(fmaxf(ix, 0.0f), (float)(WW - 1));
    iy = fminf(fmaxf(iy, 0.0f), (float)(HH - 1));
    float x0f = floorf(ix), y0f = floorf(iy);
    float wx = ix - x0f, wy = iy - y0f;
    int x0 = min(max((int)x0f, 0), WW - 1);
    int y0 = min(max((int)y0f, 0), HH - 1);
    int x1 = min(x0 + 1, WW - 1);
    int y1 = min(y0 + 1, HH - 1);

    const float* base = g_featT + (size_t)b * HWSZ * CC;
    const float* p00 = base + (size_t)(y0 * WW + x0) * CC;
    const float* p01 = base + (size_t)(y0 * WW + x1) * CC;
    const float* p10 = base + (size_t)(y1 * WW + x0) * CC;
    const float* p11 = base + (size_t)(y1 * WW + x1) * CC;

    float omx = 1.0f - wx, omy = 1.0f - wy;
    float rr[8];
#pragma unroll
    for (int q = 0; q < 2; q++) {
        int c = lane * 8 + q * 4;
        float4 a00 = *(const float4*)(p00 + c);
        float4 a01 = *(const float4*)(p01 + c);
        float4 a10 = *(const float4*)(p10 + c);
        float4 a11 = *(const float4*)(p11 + c);
        rr[q * 4 + 0] = (a00.x * omx + a01.x * wx) * omy + (a10.x * omx + a11.x * wx) * wy;
        rr[q * 4 + 1] = (a00.y * omx + a01.y * wx) * omy + (a10.y * omx + a11.y * wx) * wy;
        rr[q * 4 + 2] = (a00.z * omx + a01.z * wx) * omy + (a10.z * omx + a11.z * wx) * wy;
        rr[q * 4 + 3] = (a00.w * omx + a01.w * wx) * omy + (a10.w * omx + a11.w * wx) * wy;
    }
    uint32_t hw[4], lw[4];
#pragma unroll
    for (int t = 0; t < 4; t++) {
        __nv_bfloat162 h2 = __floats2bfloat162_rn(rr[2 * t], rr[2 * t + 1]);
        float l0 = rr[2 * t] - __bfloat162float(h2.x);
        float l1 = rr[2 * t + 1] - __bfloat162float(h2.y);
        __nv_bfloat162 l2 = __floats2bfloat162_rn(l0, l1);
        hw[t] = reinterpret_cast<uint32_t&>(h2);
        lw[t] = reinterpret_cast<uint32_t&>(l2);
    }
    size_t o = (size_t)v * CC + lane * 8;
    *(uint4*)(OAh + o) = make_uint4(hw[0], hw[1], hw[2], hw[3]);
    *(uint4*)(OAl + o) = make_uint4(lw[0], lw[1], lw[2], lw[3]);
}

// ---------------------------------------------------------------------------
// K3: weight prep -> Wt[n*K+k] = W[k*Nd+n] as bf16 hi/lo
// ---------------------------------------------------------------------------
__global__ void prep_weights(const float* __restrict__ W1, const float* __restrict__ W2,
                             const float* __restrict__ Wp) {
    int idx = blockIdx.x * 256 + threadIdx.x;
    int w = blockIdx.y;
    const float* W = (w == 0) ? W1 : (w == 1) ? W2 : Wp;
    int n = idx >> 8, k = idx & 255;
    float v = W[k * DD + n];
    __nv_bfloat16 hi = __float2bfloat16(v);
    float lo = v - __bfloat162float(hi);
    g_Whi[w][n * CC + k] = hi;
    g_Wlo[w][n * CC + k] = __float2bfloat16(lo);
}

// ---------------------------------------------------------------------------
// K4/5/6: HMMA bf16 GEMM with 3-term hi/lo split.
//   CTA tile 128x128, 8 warps x (64x32), K chunked by 32, cp.async 2-stage.
// MODE 0: relu -> bf16 split   MODE 1: +pos_enc -> bf16 split   MODE 2: fp32 out
// ---------------------------------------------------------------------------
#define GBK 32
#define ROWB 80                 // smem bytes per row: (32+8) bf16 — conflict-free LDSM
#define ASZ (128 * ROWB)        // 10240 B per operand-split per stage
#define SSTAGE (4 * ASZ)        // 40960 B per stage (Ah, Al, Bh, Bl)
#define GSMEM (2 * SSTAGE)      // 81920 B

__device__ __forceinline__ void split_store(__nv_bfloat16* Oh, __nv_bfloat16* Ol,
                                            size_t off, float a, float b) {
    __nv_bfloat162 h = __floats2bfloat162_rn(a, b);
    float la = a - __bfloat162float(h.x);
    float lb = b - __bfloat162float(h.y);
    __nv_bfloat162 l = __floats2bfloat162_rn(la, lb);
    *(__nv_bfloat162*)(Oh + off) = h;
    *(__nv_bfloat162*)(Ol + off) = l;
}

template <int MODE>
__global__ void __launch_bounds__(256, 2)
hmma_gemm(const __nv_bfloat16* __restrict__ Ah, const __nv_bfloat16* __restrict__ Al,
          const __nv_bfloat16* __restrict__ Bh, const __nv_bfloat16* __restrict__ Bl,
          const float* __restrict__ bias, float* __restrict__ OutF,
          __nv_bfloat16* __restrict__ OAh, __nv_bfloat16* __restrict__ OAl,
          const float* __restrict__ verts, const int* __restrict__ imgp) {
    extern __shared__ char smem[];
    const uint32_t sb = smem_u32(smem);
    const int tid = threadIdx.x;
    const int brow = blockIdx.x * 128;
    const int bcol = blockIdx.y * 128;
    const int warp = tid >> 5, lane = tid & 31;
    const int wm = warp >> 2, wn = warp & 3;  // 2 x 4 warps -> 64x32 tiles

    const __nv_bfloat16* gsrc[4] = {
        Ah + (size_t)brow * CC, Al + (size_t)brow * CC,
        Bh + (size_t)bcol * CC, Bl + (size_t)bcol * CC};

    float acc[4][4][4];
#pragma unroll
    for (int i = 0; i < 4; i++)
#pragma unroll
        for (int j = 0; j < 4; j++)
#pragma unroll
            for (int q = 0; q < 4; q++) acc[i][j][q] = 0.0f;

    // ---- cp.async stage loader ----
    auto load_stage = [&](int buf, int chunk) {
#pragma unroll
        for (int arr = 0; arr < 4; arr++) {
            uint32_t dbase = sb + buf * SSTAGE + arr * ASZ;
            const __nv_bfloat16* g = gsrc[arr];
#pragma unroll
            for (int i = 0; i < 2; i++) {
                int idx = tid * 2 + i;
                int r = idx >> 2, q = idx & 3;
                cpa16(dbase + r * ROWB + q * 16,
                      g + (size_t)r * CC + chunk * GBK + q * 8);
            }
        }
    };

    load_stage(0, 0);
    CP_COMMIT();
    load_stage(1, 1);
    CP_COMMIT();

    // ldmatrix lane addressing (computed once)
    const int a_row = wm * 64 + (lane & 15);
    const int a_colh = (lane >> 4) << 3;                       // 0 or 8 (k elems)
    const int b_row = wn * 32 + (lane & 7) + ((lane >> 4) << 3);
    const int b_colh = ((lane >> 3) & 1) << 3;

    for (int c = 0; c < 8; c++) {
        CP_WAIT1();
        __syncthreads();
        const uint32_t st = sb + (c & 1) * SSTAGE;
#pragma unroll
        for (int ks = 0; ks < 2; ks++) {
            uint32_t bfr[4][2], bfl[4][2], af[4][4];
            // B hi frags (4 n-tiles via 2 x LDSM.x4)
#pragma unroll
            for (int nt2 = 0; nt2 < 2; nt2++) {
                uint32_t addr = st + 2 * ASZ + (b_row + nt2 * 16) * ROWB +
                                (ks * 16 + b_colh) * 2;
                ldsm4(addr, bfr[2 * nt2][0], bfr[2 * nt2][1],
                      bfr[2 * nt2 + 1][0], bfr[2 * nt2 + 1][1]);
            }
            // B lo frags
#pragma unroll
            for (int nt2 = 0; nt2 < 2; nt2++) {
                uint32_t addr = st + 3 * ASZ + (b_row + nt2 * 16) * ROWB +
                                (ks * 16 + b_colh) * 2;
                ldsm4(addr, bfl[2 * nt2][0], bfl[2 * nt2][1],
                      bfl[2 * nt2 + 1][0], bfl[2 * nt2 + 1][1]);
            }
            // A hi frags
#pragma unroll
            for (int mt = 0; mt < 4; mt++) {
                uint32_t addr = st + (a_row + mt * 16) * ROWB + (ks * 16 + a_colh) * 2;
                ldsm4(addr, af[mt][0], af[mt][1], af[mt][2], af[mt][3]);
            }
            // split 0: Ahi * Bhi
#pragma unroll
            for (int mt = 0; mt < 4; mt++)
#pragma unroll
                for (int nt = 0; nt < 4; nt++) mma16816(acc[mt][nt], af[mt], bfr[nt]);
            // split 1: Ahi * Blo
#pragma unroll
            for (int mt = 0; mt < 4; mt++)
#pragma unroll
                for (int nt = 0; nt < 4; nt++) mma16816(acc[mt][nt], af[mt], bfl[nt]);
            // A lo frags (reuse regs)
#pragma unroll
            for (int mt = 0; mt < 4; mt++) {
                uint32_t addr = st + ASZ + (a_row + mt * 16) * ROWB + (ks * 16 + a_colh) * 2;
                ldsm4(addr, af[mt][0], af[mt][1], af[mt][2], af[mt][3]);
            }
            // split 2: Alo * Bhi
#pragma unroll
            for (int mt = 0; mt < 4; mt++)
#pragma unroll
                for (int nt = 0; nt < 4; nt++) mma16816(acc[mt][nt], af[mt], bfr[nt]);
        }
        __syncthreads();
        if (c < 6) load_stage(c & 1, c + 2);
        CP_COMMIT();
    }

    // ---- epilogue (register-resident accumulators) ----
    const int rbase = brow + wm * 64 + (lane >> 2);
    const int cbase = bcol + wn * 32 + (lane & 3) * 2;
    float img = 1.0f;
    int coff = 0;
    if (MODE == 1) {
        img = read_img(imgp);
        coff = bcol >> 7;  // cols 0-127 <- x, 128-255 <- y
    }
#pragma unroll
    for (int mt = 0; mt < 4; mt++) {
        int r0 = rbase + mt * 16;
        int r1 = r0 + 8;
        float x0 = 0.0f, x1 = 0.0f;
        if (MODE == 1) {
            x0 = (verts[2 * r0 + coff] / img) * 1000.0f;
            x1 = (verts[2 * r1 + coff] / img) * 1000.0f;
        }
#pragma unroll
        for (int nt = 0; nt < 4; nt++) {
            int col = cbase + nt * 8;
            float b0 = __ldg(&bias[col]), b1 = __ldg(&bias[col + 1]);
            float v00 = acc[mt][nt][0] + b0, v01 = acc[mt][nt][1] + b1;
            float v10 = acc[mt][nt][2] + b0, v11 = acc[mt][nt][3] + b1;
            if (MODE == 0) {
                v00 = fmaxf(v00, 0.0f); v01 = fmaxf(v01, 0.0f);
                v10 = fmaxf(v10, 0.0f); v11 = fmaxf(v11, 0.0f);
            }
            if (MODE == 1) {
                int f = (col & 127) >> 1;
                float fr = exp2f(-(float)f * 0.20762050593046015f);  // 10000^(-f/64)
                float a0 = x0 * fr, a1 = x1 * fr;
                float k0 = rintf(a0 * 0.15915494309189535f);
                float q0 = fmaf(-k0, 6.2831854820251465f, a0);
                q0 = fmaf(-k0, -1.7484555e-07f, q0);
                float k1 = rintf(a1 * 0.15915494309189535f);
                float q1 = fmaf(-k1, 6.2831854820251465f, a1);
                q1 = fmaf(-k1, -1.7484555e-07f, q1);
                v00 += __sinf(q0); v01 += __cosf(q0);
                v10 += __sinf(q1); v11 += __cosf(q1);
            }
            if (MODE == 2) {
                *(float2*)(OutF + (size_t)r0 * DD + col) = make_float2(v00, v01);
                *(float2*)(OutF + (size_t)r1 * DD + col) = make_float2(v10, v11);
            } else {
                split_store(OAh, OAl, (size_t)r0 * DD + col, v00, v01);
                split_store(OAh, OAl, (size_t)r1 * DD + col, v10, v11);
            }
        }
    }
}

// ---------------------------------------------------------------------------
extern "C" void kernel_launch(void* const* d_in, const int* in_sizes, int n_in,
                              void* d_out, int out_size) {
    const float* features = (const float*)d_in[0];
    const float* vertices = (const float*)d_in[1];
    const int* imgp = (const int*)d_in[2];
    const float* W1 = (const float*)d_in[3];
    const float* b1 = (const float*)d_in[4];
    const float* W2 = (const float*)d_in[5];
    const float* b2 = (const float*)d_in[6];
    const float* Wp = (const float*)d_in[7];
    const float* bp = (const float*)d_in[8];
    float* out = (float*)d_out;

    void *pAh, *pAl, *pCh, *pCl, *pWh, *pWl;
    cudaGetSymbolAddress(&pAh, g_Ahi);
    cudaGetSymbolAddress(&pAl, g_Alo);
    cudaGetSymbolAddress(&pCh, g_Chi);
    cudaGetSymbolAddress(&pCl, g_Clo);
    cudaGetSymbolAddress(&pWh, g_Whi);
    cudaGetSymbolAddress(&pWl, g_Wlo);
    __nv_bfloat16* Ahi = (__nv_bfloat16*)pAh;
    __nv_bfloat16* Alo = (__nv_bfloat16*)pAl;
    __nv_bfloat16* Chi = (__nv_bfloat16*)pCh;
    __nv_bfloat16* Clo = (__nv_bfloat16*)pCl;
    __nv_bfloat16* Whi = (__nv_bfloat16*)pWh;
    __nv_bfloat16* Wlo = (__nv_bfloat16*)pWl;

    cudaFuncSetAttribute(hmma_gemm<0>, cudaFuncAttributeMaxDynamicSharedMemorySize, GSMEM);
    cudaFuncSetAttribute(hmma_gemm<1>, cudaFuncAttributeMaxDynamicSharedMemorySize, GSMEM);
    cudaFuncSetAttribute(hmma_gemm<2>, cudaFuncAttributeMaxDynamicSharedMemorySize, GSMEM);

    transpose_kernel<<<dim3(HWSZ / 32, CC / 32, BB), dim3(32, 8)>>>(features);
    gather_kernel<<<MROWS / 4, 128>>>(vertices, imgp, Ahi, Alo);
    prep_weights<<<dim3(DD * CC / 256, 3), 256>>>(W1, W2, Wp);

    dim3 gg(MROWS / 128, DD / 128);
    // GEMM1: sampled @ W1 + b1, relu  (ping -> pong)
    hmma_gemm<0><<<gg, 256, GSMEM>>>(Ahi, Alo, Whi + 0 * (size_t)DD * CC,
                                     Wlo + 0 * (size_t)DD * CC, b1, nullptr,
                                     Chi, Clo, vertices, imgp);
    // GEMM2: h @ W2 + b2 + pos_enc   (pong -> ping)
    hmma_gemm<1><<<gg, 256, GSMEM>>>(Chi, Clo, Whi + 1 * (size_t)DD * CC,
                                     Wlo + 1 * (size_t)DD * CC, b2, nullptr,
                                     Ahi, Alo, vertices, imgp);
    // GEMM3: (vfeat+pos) @ Wp + bp -> fp32 out
    hmma_gemm<2><<<gg, 256, GSMEM>>>(Ahi, Alo, Whi + 2 * (size_t)DD * CC,
                                     Wlo + 2 * (size_t)DD * CC, bp, out,
                                     nullptr, nullptr, vertices, imgp);
}

// round 4
// speedup vs baseline: 2.2498x; 1.3390x over previous
#include <cuda_runtime.h>
#include <cuda_bf16.h>
#include <cstdint>

#define BB 16
#define CC 256
#define HH 128
#define WW 128
#define NV 4096
#define DD 256
#define MROWS (BB * NV)   // 65536
#define HWSZ (HH * WW)    // 16384

// ---------------- scratch (static __device__: allocation-free) ----------------
__device__ float g_featT[(size_t)BB * HWSZ * CC];       // 256 MiB transposed features (B,HW,C)
__device__ __nv_bfloat16 g_Ahi[(size_t)MROWS * CC];     // activations ping (hi)
__device__ __nv_bfloat16 g_Alo[(size_t)MROWS * CC];     // activations ping (lo)
__device__ __nv_bfloat16 g_Chi[(size_t)MROWS * CC];     // activations pong (hi)
__device__ __nv_bfloat16 g_Clo[(size_t)MROWS * CC];     // activations pong (lo)
__device__ __nv_bfloat16 g_Whi[3][DD * CC];             // weights [N,K] K-major, hi
__device__ __nv_bfloat16 g_Wlo[3][DD * CC];             // weights lo

__device__ __forceinline__ float read_img(const int* p) {
    int iv = *p;
    if (iv > 1 && iv < (1 << 24)) return (float)iv;
    return __int_as_float(iv);
}

// ---------------- family-agnostic PTX helpers (sm_80+) ----------------
__device__ __forceinline__ uint32_t smem_u32(const void* p) {
    uint32_t a;
    asm("{ .reg .u64 t; cvta.to.shared.u64 t, %1; cvt.u32.u64 %0, t; }" : "=r"(a) : "l"(p));
    return a;
}
__device__ __forceinline__ void cpa16(uint32_t dst, const void* src) {
    asm volatile("cp.async.cg.shared.global [%0], [%1], 16;" :: "r"(dst), "l"(src));
}
#define CP_COMMIT() asm volatile("cp.async.commit_group;" ::: "memory")
#define CP_WAIT1() asm volatile("cp.async.wait_group 1;" ::: "memory")

__device__ __forceinline__ void ldsm4(uint32_t a, uint32_t& r0, uint32_t& r1,
                                      uint32_t& r2, uint32_t& r3) {
    asm volatile("ldmatrix.sync.aligned.m8n8.x4.shared.b16 {%0,%1,%2,%3}, [%4];"
                 : "=r"(r0), "=r"(r1), "=r"(r2), "=r"(r3) : "r"(a));
}
__device__ __forceinline__ void mma16816(float* c, const uint32_t* a, const uint32_t* b) {
    asm volatile(
        "mma.sync.aligned.m16n8k16.row.col.f32.bf16.bf16.f32 "
        "{%0,%1,%2,%3}, {%4,%5,%6,%7}, {%8,%9}, {%0,%1,%2,%3};"
        : "+f"(c[0]), "+f"(c[1]), "+f"(c[2]), "+f"(c[3])
        : "r"(a[0]), "r"(a[1]), "r"(a[2]), "r"(a[3]), "r"(b[0]), "r"(b[1]));
}

// ---------------------------------------------------------------------------
// K1: transpose (B,C,H,W) -> (B,HW,C) fp32 — float4 both global sides
// ---------------------------------------------------------------------------
__global__ void __launch_bounds__(256) transpose_kernel(const float* __restrict__ src) {
    __shared__ float sm[64 * 65];
    int b = blockIdx.z;
    int hw0 = blockIdx.x * 64;
    int c0 = blockIdx.y * 64;
    const float* s = src + (size_t)b * CC * HWSZ;
    float* d = g_featT + (size_t)b * HWSZ * CC;
    int tid = threadIdx.x;
#pragma unroll
    for (int i = 0; i < 4; i++) {
        int idx = tid + i * 256;
        int r = idx >> 4, q = idx & 15;   // r = channel row, q = hw quad
        float4 v = *(const float4*)(s + (size_t)(c0 + r) * HWSZ + hw0 + q * 4);
        float* p = &sm[r * 65 + q * 4];
        p[0] = v.x; p[1] = v.y; p[2] = v.z; p[3] = v.w;
    }
    __syncthreads();
#pragma unroll
    for (int i = 0; i < 4; i++) {
        int idx = tid + i * 256;
        int r = idx >> 4, q = idx & 15;   // r = hw row, q = channel quad
        float4 v;
        v.x = sm[(q * 4 + 0) * 65 + r];
        v.y = sm[(q * 4 + 1) * 65 + r];
        v.z = sm[(q * 4 + 2) * 65 + r];
        v.w = sm[(q * 4 + 3) * 65 + r];
        *(float4*)(d + (size_t)(hw0 + r) * CC + c0 + q * 4) = v;
    }
}

// ---------------------------------------------------------------------------
// K2: bilinear gather -> hi/lo bf16 split (GEMM1 A operand produced directly)
// ---------------------------------------------------------------------------
__global__ void gather_kernel(const float* __restrict__ verts,
                              const int* __restrict__ imgp,
                              __nv_bfloat16* __restrict__ OAh,
                              __nv_bfloat16* __restrict__ OAl) {
    int v = blockIdx.x * 4 + (threadIdx.x >> 5);
    int lane = threadIdx.x & 31;
    int b = v >> 12;

    float img = read_img(imgp);
    float denom = img - 1.0f;
    float gx = 2.0f * verts[2 * v + 0] / denom - 1.0f;
    float gy = 2.0f * verts[2 * v + 1] / denom - 1.0f;
    float ix = (gx + 1.0f) * 0.5f * (float)(WW - 1);
    float iy = (gy + 1.0f) * 0.5f * (float)(HH - 1);
    ix = fminf(fmaxf(ix, 0.0f), (float)(WW - 1));
    iy = fminf(fmaxf(iy, 0.0f), (float)(HH - 1));
    float x0f = floorf(ix), y0f = floorf(iy);
    float wx = ix - x0f, wy = iy - y0f;
    int x0 = min(max((int)x0f, 0), WW - 1);
    int y0 = min(max((int)y0f, 0), HH - 1);
    int x1 = min(x0 + 1, WW - 1);
    int y1 = min(y0 + 1, HH - 1);

    const float* base = g_featT + (size_t)b * HWSZ * CC;
    const float* p00 = base + (size_t)(y0 * WW + x0) * CC;
    const float* p01 = base + (size_t)(y0 * WW + x1) * CC;
    const float* p10 = base + (size_t)(y1 * WW + x0) * CC;
    const float* p11 = base + (size_t)(y1 * WW + x1) * CC;

    float omx = 1.0f - wx, omy = 1.0f - wy;
    float rr[8];
#pragma unroll
    for (int q = 0; q < 2; q++) {
        int c = lane * 8 + q * 4;
        float4 a00 = *(const float4*)(p00 + c);
        float4 a01 = *(const float4*)(p01 + c);
        float4 a10 = *(const float4*)(p10 + c);
        float4 a11 = *(const float4*)(p11 + c);
        rr[q * 4 + 0] = (a00.x * omx + a01.x * wx) * omy + (a10.x * omx + a11.x * wx) * wy;
        rr[q * 4 + 1] = (a00.y * omx + a01.y * wx) * omy + (a10.y * omx + a11.y * wx) * wy;
        rr[q * 4 + 2] = (a00.z * omx + a01.z * wx) * omy + (a10.z * omx + a11.z * wx) * wy;
        rr[q * 4 + 3] = (a00.w * omx + a01.w * wx) * omy + (a10.w * omx + a11.w * wx) * wy;
    }
    uint32_t hw[4], lw[4];
#pragma unroll
    for (int t = 0; t < 4; t++) {
        __nv_bfloat162 h2 = __floats2bfloat162_rn(rr[2 * t], rr[2 * t + 1]);
        float l0 = rr[2 * t] - __bfloat162float(h2.x);
        float l1 = rr[2 * t + 1] - __bfloat162float(h2.y);
        __nv_bfloat162 l2 = __floats2bfloat162_rn(l0, l1);
        hw[t] = reinterpret_cast<uint32_t&>(h2);
        lw[t] = reinterpret_cast<uint32_t&>(l2);
    }
    size_t o = (size_t)v * CC + lane * 8;
    *(uint4*)(OAh + o) = make_uint4(hw[0], hw[1], hw[2], hw[3]);
    *(uint4*)(OAl + o) = make_uint4(lw[0], lw[1], lw[2], lw[3]);
}

// ---------------------------------------------------------------------------
// K3: weight prep -> Wt[n*K+k] = W[k*Nd+n] as bf16 hi/lo
// ---------------------------------------------------------------------------
__global__ void prep_weights(const float* __restrict__ W1, const float* __restrict__ W2,
                             const float* __restrict__ Wp) {
    int idx = blockIdx.x * 256 + threadIdx.x;
    int w = blockIdx.y;
    const float* W = (w == 0) ? W1 : (w == 1) ? W2 : Wp;
    int n = idx >> 8, k = idx & 255;
    float v = W[k * DD + n];
    __nv_bfloat16 hi = __float2bfloat16(v);
    float lo = v - __bfloat162float(hi);
    g_Whi[w][n * CC + k] = hi;
    g_Wlo[w][n * CC + k] = __float2bfloat16(lo);
}

// ---------------------------------------------------------------------------
// K4/5/6: HMMA bf16 GEMM, 3-term hi/lo split, SW128-swizzled packed rows.
//   smem row (128B) = [hi 32 k-elems | lo 32 k-elems]; chunk swizzle c^(r&7).
//   3-stage cp.async pipeline, depth-2 prefetch, ONE syncthreads per chunk.
// MODE 0: relu -> bf16 split   MODE 1: +pos_enc -> bf16 split   MODE 2: fp32 out
// ---------------------------------------------------------------------------
#define GBK 32
#define STAGEB 32768            // A 16 KB + B 16 KB
#define GSMEM (3 * STAGEB)      // 98304

__device__ __forceinline__ void split_store(__nv_bfloat16* Oh, __nv_bfloat16* Ol,
                                            size_t off, float a, float b) {
    __nv_bfloat162 h = __floats2bfloat162_rn(a, b);
    float la = a - __bfloat162float(h.x);
    float lb = b - __bfloat162float(h.y);
    __nv_bfloat162 l = __floats2bfloat162_rn(la, lb);
    *(__nv_bfloat162*)(Oh + off) = h;
    *(__nv_bfloat162*)(Ol + off) = l;
}

template <int MODE>
__global__ void __launch_bounds__(256, 2)
hmma_gemm(const __nv_bfloat16* __restrict__ Ah, const __nv_bfloat16* __restrict__ Al,
          const __nv_bfloat16* __restrict__ Bh, const __nv_bfloat16* __restrict__ Bl,
          const float* __restrict__ bias, float* __restrict__ OutF,
          __nv_bfloat16* __restrict__ OAh, __nv_bfloat16* __restrict__ OAl,
          const float* __restrict__ verts, const int* __restrict__ imgp) {
    extern __shared__ char smem[];
    const uint32_t sb = smem_u32(smem);
    const int tid = threadIdx.x;
    const int brow = blockIdx.x * 128;
    const int bcol = blockIdx.y * 128;
    const int warp = tid >> 5, lane = tid & 31;
    const int wm = warp >> 2, wn = warp & 3;  // 2 x 4 warps -> 64x32 warp tiles

    float acc[4][4][4];
#pragma unroll
    for (int i = 0; i < 4; i++)
#pragma unroll
        for (int j = 0; j < 4; j++)
#pragma unroll
            for (int q = 0; q < 4; q++) acc[i][j][q] = 0.0f;

    // ---- stage loader: rows swizzled SW128; row = [hi 64B | lo 64B] ----
    const int ldr = tid >> 3;        // 0..31 (row within 128 via +i*32)
    const int ldc = tid & 7;         // chunk 0..7
    auto load_stage = [&](int s, int chunk) {
        uint32_t dst = sb + s * STAGEB;
        const __nv_bfloat16* ga = (ldc < 4) ? Ah : Al;
        const __nv_bfloat16* gb = (ldc < 4) ? Bh : Bl;
        uint32_t cofs = ((uint32_t)chunk << 5) + ((ldc & 3) << 3);
#pragma unroll
        for (int i = 0; i < 4; i++) {
            int row = ldr + i * 32;
            uint32_t sw = (uint32_t)(row << 7) + (((uint32_t)(ldc ^ (row & 7))) << 4);
            cpa16(dst + sw, ga + (size_t)(brow + row) * CC + cofs);
            cpa16(dst + 16384 + sw, gb + (size_t)(bcol + row) * CC + cofs);
        }
    };

    // ---- precomputed ldsm bases (swizzle folded per-lane) ----
    uint32_t aBase[4], bBase[2];
#pragma unroll
    for (int mt = 0; mt < 4; mt++) {
        int row = wm * 64 + mt * 16 + (lane & 15);
        aBase[mt] = (uint32_t)(row << 7) + ((uint32_t)(((row & 7) ^ (lane >> 4))) << 4);
    }
#pragma unroll
    for (int nt2 = 0; nt2 < 2; nt2++) {
        int row = wn * 32 + nt2 * 16 + (lane & 7) + ((lane >> 4) << 3);
        bBase[nt2] = 16384u + (uint32_t)(row << 7) +
                     ((uint32_t)(((row & 7) ^ ((lane >> 3) & 1))) << 4);
    }

    load_stage(0, 0);
    CP_COMMIT();
    load_stage(1, 1);
    CP_COMMIT();

    for (int c = 0; c < 8; c++) {
        CP_WAIT1();
        __syncthreads();
        // prefetch chunk c+2 into buffer (c+2)%3 (its old contents, chunk c-1,
        // were consumed by everyone before this iteration's barrier)
        if (c + 2 < 8) load_stage((c + 2) % 3, c + 2);
        CP_COMMIT();

        const uint32_t st = sb + (c % 3) * STAGEB;
#pragma unroll
        for (int ks = 0; ks < 2; ks++) {
            const uint32_t kx = (uint32_t)(ks << 5);
            uint32_t bfr[4][2], bfl[4][2], af[4][4];
#pragma unroll
            for (int nt2 = 0; nt2 < 2; nt2++) {
                uint32_t a = (st + bBase[nt2]) ^ kx;
                ldsm4(a, bfr[2 * nt2][0], bfr[2 * nt2][1],
                      bfr[2 * nt2 + 1][0], bfr[2 * nt2 + 1][1]);
                ldsm4(a ^ 64u, bfl[2 * nt2][0], bfl[2 * nt2][1],
                      bfl[2 * nt2 + 1][0], bfl[2 * nt2 + 1][1]);
            }
#pragma unroll
            for (int mt = 0; mt < 4; mt++) {
                uint32_t a = (st + aBase[mt]) ^ kx;
                ldsm4(a, af[mt][0], af[mt][1], af[mt][2], af[mt][3]);
            }
            // Ahi*Bhi and Ahi*Blo
#pragma unroll
            for (int mt = 0; mt < 4; mt++)
#pragma unroll
                for (int nt = 0; nt < 4; nt++) mma16816(acc[mt][nt], af[mt], bfr[nt]);
#pragma unroll
            for (int mt = 0; mt < 4; mt++)
#pragma unroll
                for (int nt = 0; nt < 4; nt++) mma16816(acc[mt][nt], af[mt], bfl[nt]);
            // Alo*Bhi (reuse af regs)
#pragma unroll
            for (int mt = 0; mt < 4; mt++) {
                uint32_t a = ((st + aBase[mt]) ^ kx) ^ 64u;
                ldsm4(a, af[mt][0], af[mt][1], af[mt][2], af[mt][3]);
            }
#pragma unroll
            for (int mt = 0; mt < 4; mt++)
#pragma unroll
                for (int nt = 0; nt < 4; nt++) mma16816(acc[mt][nt], af[mt], bfr[nt]);
        }
    }

    // ---- epilogue (register-resident accumulators) ----
    const int rbase = brow + wm * 64 + (lane >> 2);
    const int cbase = bcol + wn * 32 + (lane & 3) * 2;
    float img = 1.0f;
    int coff = 0;
    if (MODE == 1) {
        img = read_img(imgp);
        coff = bcol >> 7;  // cols 0-127 <- x, 128-255 <- y
    }
#pragma unroll
    for (int mt = 0; mt < 4; mt++) {
        int r0 = rbase + mt * 16;
        int r1 = r0 + 8;
        float x0 = 0.0f, x1 = 0.0f;
        if (MODE == 1) {
            x0 = (verts[2 * r0 + coff] / img) * 1000.0f;
            x1 = (verts[2 * r1 + coff] / img) * 1000.0f;
        }
#pragma unroll
        for (int nt = 0; nt < 4; nt++) {
            int col = cbase + nt * 8;
            float b0 = __ldg(&bias[col]), b1 = __ldg(&bias[col + 1]);
            float v00 = acc[mt][nt][0] + b0, v01 = acc[mt][nt][1] + b1;
            float v10 = acc[mt][nt][2] + b0, v11 = acc[mt][nt][3] + b1;
            if (MODE == 0) {
                v00 = fmaxf(v00, 0.0f); v01 = fmaxf(v01, 0.0f);
                v10 = fmaxf(v10, 0.0f); v11 = fmaxf(v11, 0.0f);
            }
            if (MODE == 1) {
                int f = (col & 127) >> 1;
                float fr = exp2f(-(float)f * 0.20762050593046015f);  // 10000^(-f/64)
                float a0 = x0 * fr, a1 = x1 * fr;
                float k0 = rintf(a0 * 0.15915494309189535f);
                float q0 = fmaf(-k0, 6.2831854820251465f, a0);
                q0 = fmaf(-k0, -1.7484555e-07f, q0);
                float k1 = rintf(a1 * 0.15915494309189535f);
                float q1 = fmaf(-k1, 6.2831854820251465f, a1);
                q1 = fmaf(-k1, -1.7484555e-07f, q1);
                v00 += __sinf(q0); v01 += __cosf(q0);
                v10 += __sinf(q1); v11 += __cosf(q1);
            }
            if (MODE == 2) {
                *(float2*)(OutF + (size_t)r0 * DD + col) = make_float2(v00, v01);
                *(float2*)(OutF + (size_t)r1 * DD + col) = make_float2(v10, v11);
            } else {
                split_store(OAh, OAl, (size_t)r0 * DD + col, v00, v01);
                split_store(OAh, OAl, (size_t)r1 * DD + col, v10, v11);
            }
        }
    }
}

// ---------------------------------------------------------------------------
extern "C" void kernel_launch(void* const* d_in, const int* in_sizes, int n_in,
                              void* d_out, int out_size) {
    const float* features = (const float*)d_in[0];
    const float* vertices = (const float*)d_in[1];
    const int* imgp = (const int*)d_in[2];
    const float* W1 = (const float*)d_in[3];
    const float* b1 = (const float*)d_in[4];
    const float* W2 = (const float*)d_in[5];
    const float* b2 = (const float*)d_in[6];
    const float* Wp = (const float*)d_in[7];
    const float* bp = (const float*)d_in[8];
    float* out = (float*)d_out;

    void *pAh, *pAl, *pCh, *pCl, *pWh, *pWl;
    cudaGetSymbolAddress(&pAh, g_Ahi);
    cudaGetSymbolAddress(&pAl, g_Alo);
    cudaGetSymbolAddress(&pCh, g_Chi);
    cudaGetSymbolAddress(&pCl, g_Clo);
    cudaGetSymbolAddress(&pWh, g_Whi);
    cudaGetSymbolAddress(&pWl, g_Wlo);
    __nv_bfloat16* Ahi = (__nv_bfloat16*)pAh;
    __nv_bfloat16* Alo = (__nv_bfloat16*)pAl;
    __nv_bfloat16* Chi = (__nv_bfloat16*)pCh;
    __nv_bfloat16* Clo = (__nv_bfloat16*)pCl;
    __nv_bfloat16* Whi = (__nv_bfloat16*)pWh;
    __nv_bfloat16* Wlo = (__nv_bfloat16*)pWl;

    cudaFuncSetAttribute(hmma_gemm<0>, cudaFuncAttributeMaxDynamicSharedMemorySize, GSMEM);
    cudaFuncSetAttribute(hmma_gemm<1>, cudaFuncAttributeMaxDynamicSharedMemorySize, GSMEM);
    cudaFuncSetAttribute(hmma_gemm<2>, cudaFuncAttributeMaxDynamicSharedMemorySize, GSMEM);

    transpose_kernel<<<dim3(HWSZ / 64, CC / 64, BB), 256>>>(features);
    gather_kernel<<<MROWS / 4, 128>>>(vertices, imgp, Ahi, Alo);
    prep_weights<<<dim3(DD * CC / 256, 3), 256>>>(W1, W2, Wp);

    dim3 gg(MROWS / 128, DD / 128);
    // GEMM1: sampled @ W1 + b1, relu  (ping -> pong)
    hmma_gemm<0><<<gg, 256, GSMEM>>>(Ahi, Alo, Whi + 0 * (size_t)DD * CC,
                                     Wlo + 0 * (size_t)DD * CC, b1, nullptr,
                                     Chi, Clo, vertices, imgp);
    // GEMM2: h @ W2 + b2 + pos_enc   (pong -> ping)
    hmma_gemm<1><<<gg, 256, GSMEM>>>(Chi, Clo, Whi + 1 * (size_t)DD * CC,
                                     Wlo + 1 * (size_t)DD * CC, b2, nullptr,
                                     Ahi, Alo, vertices, imgp);
    // GEMM3: (vfeat+pos) @ Wp + bp -> fp32 out
    hmma_gemm<2><<<gg, 256, GSMEM>>>(Ahi, Alo, Whi + 2 * (size_t)DD * CC,
                                     Wlo + 2 * (size_t)DD * CC, bp, out,
                                     nullptr, nullptr, vertices, imgp);
}

// round 5
// speedup vs baseline: 2.5479x; 1.1325x over previous
#include <cuda_runtime.h>
#include <cuda_bf16.h>
#include <cuda_fp16.h>
#include <cstdint>

#define BB 16
#define CC 256
#define HH 128
#define WW 128
#define NV 4096
#define DD 256
#define MROWS (BB * NV)   // 65536
#define HWSZ (HH * WW)    // 16384

// ---------------- scratch (static __device__: allocation-free) ----------------
__device__ __half g_featT[(size_t)BB * HWSZ * CC];      // 128 MiB transposed features (B,HW,C) fp16
__device__ __nv_bfloat16 g_Ahi[(size_t)MROWS * CC];     // activations ping (hi)
__device__ __nv_bfloat16 g_Alo[(size_t)MROWS * CC];     // activations ping (lo)
__device__ __nv_bfloat16 g_Chi[(size_t)MROWS * CC];     // activations pong (hi)
__device__ __nv_bfloat16 g_Clo[(size_t)MROWS * CC];     // activations pong (lo)
__device__ __nv_bfloat16 g_Whi[3][DD * CC];             // weights [N,K] K-major, hi
__device__ __nv_bfloat16 g_Wlo[3][DD * CC];             // weights lo

__device__ __forceinline__ float read_img(const int* p) {
    int iv = *p;
    if (iv > 1 && iv < (1 << 24)) return (float)iv;
    return __int_as_float(iv);
}

// ---------------- family-agnostic PTX helpers (sm_80+) ----------------
__device__ __forceinline__ uint32_t smem_u32(const void* p) {
    uint32_t a;
    asm("{ .reg .u64 t; cvta.to.shared.u64 t, %1; cvt.u32.u64 %0, t; }" : "=r"(a) : "l"(p));
    return a;
}
__device__ __forceinline__ void cpa16(uint32_t dst, const void* src) {
    asm volatile("cp.async.cg.shared.global [%0], [%1], 16;" :: "r"(dst), "l"(src));
}
#define CP_COMMIT() asm volatile("cp.async.commit_group;" ::: "memory")
#define CP_WAIT1() asm volatile("cp.async.wait_group 1;" ::: "memory")

__device__ __forceinline__ void ldsm4(uint32_t a, uint32_t& r0, uint32_t& r1,
                                      uint32_t& r2, uint32_t& r3) {
    asm volatile("ldmatrix.sync.aligned.m8n8.x4.shared.b16 {%0,%1,%2,%3}, [%4];"
                 : "=r"(r0), "=r"(r1), "=r"(r2), "=r"(r3) : "r"(a));
}
__device__ __forceinline__ void mma16816(float* c, const uint32_t* a, const uint32_t* b) {
    asm volatile(
        "mma.sync.aligned.m16n8k16.row.col.f32.bf16.bf16.f32 "
        "{%0,%1,%2,%3}, {%4,%5,%6,%7}, {%8,%9}, {%0,%1,%2,%3};"
        : "+f"(c[0]), "+f"(c[1]), "+f"(c[2]), "+f"(c[3])
        : "r"(a[0]), "r"(a[1]), "r"(a[2]), "r"(a[3]), "r"(b[0]), "r"(b[1]));
}

// ---------------------------------------------------------------------------
// K1: transpose (B,C,H,W) fp32 -> (B,HW,C) fp16 — float4 reads, uint4 fp16 writes
// ---------------------------------------------------------------------------
__global__ void __launch_bounds__(256) transpose_kernel(const float* __restrict__ src) {
    __shared__ float sm[64 * 65];
    int b = blockIdx.z;
    int hw0 = blockIdx.x * 64;
    int c0 = blockIdx.y * 64;
    const float* s = src + (size_t)b * CC * HWSZ;
    __half* d = g_featT + (size_t)b * HWSZ * CC;
    int tid = threadIdx.x;
#pragma unroll
    for (int i = 0; i < 4; i++) {
        int idx = tid + i * 256;
        int r = idx >> 4, q = idx & 15;   // r = channel row, q = hw quad
        float4 v = *(const float4*)(s + (size_t)(c0 + r) * HWSZ + hw0 + q * 4);
        float* p = &sm[r * 65 + q * 4];
        p[0] = v.x; p[1] = v.y; p[2] = v.z; p[3] = v.w;
    }
    __syncthreads();
#pragma unroll
    for (int i = 0; i < 2; i++) {
        int idx = tid + i * 256;
        int r = idx >> 3, q = idx & 7;    // r = hw row, q = channel octet
        __half2 h[4];
#pragma unroll
        for (int j = 0; j < 4; j++) {
            float a = sm[(q * 8 + 2 * j + 0) * 65 + r];
            float bb2 = sm[(q * 8 + 2 * j + 1) * 65 + r];
            h[j] = __floats2half2_rn(a, bb2);
        }
        *(uint4*)(d + (size_t)(hw0 + r) * CC + c0 + q * 8) = *(uint4*)h;
    }
}

// ---------------------------------------------------------------------------
// K2: bilinear gather (fp16 features -> fp32 interp) -> hi/lo bf16 split
// ---------------------------------------------------------------------------
__global__ void gather_kernel(const float* __restrict__ verts,
                              const int* __restrict__ imgp,
                              __nv_bfloat16* __restrict__ OAh,
                              __nv_bfloat16* __restrict__ OAl) {
    int v = blockIdx.x * 4 + (threadIdx.x >> 5);
    int lane = threadIdx.x & 31;
    int b = v >> 12;

    float img = read_img(imgp);
    float denom = img - 1.0f;
    float gx = 2.0f * verts[2 * v + 0] / denom - 1.0f;
    float gy = 2.0f * verts[2 * v + 1] / denom - 1.0f;
    float ix = (gx + 1.0f) * 0.5f * (float)(WW - 1);
    float iy = (gy + 1.0f) * 0.5f * (float)(HH - 1);
    ix = fminf(fmaxf(ix, 0.0f), (float)(WW - 1));
    iy = fminf(fmaxf(iy, 0.0f), (float)(HH - 1));
    float x0f = floorf(ix), y0f = floorf(iy);
    float wx = ix - x0f, wy = iy - y0f;
    int x0 = min(max((int)x0f, 0), WW - 1);
    int y0 = min(max((int)y0f, 0), HH - 1);
    int x1 = min(x0 + 1, WW - 1);
    int y1 = min(y0 + 1, HH - 1);

    const __half* base = g_featT + (size_t)b * HWSZ * CC;
    const __half* p00 = base + (size_t)(y0 * WW + x0) * CC + lane * 8;
    const __half* p01 = base + (size_t)(y0 * WW + x1) * CC + lane * 8;
    const __half* p10 = base + (size_t)(y1 * WW + x0) * CC + lane * 8;
    const __half* p11 = base + (size_t)(y1 * WW + x1) * CC + lane * 8;

    uint4 u00 = *(const uint4*)p00;
    uint4 u01 = *(const uint4*)p01;
    uint4 u10 = *(const uint4*)p10;
    uint4 u11 = *(const uint4*)p11;

    float omx = 1.0f - wx, omy = 1.0f - wy;
    float w00 = omx * omy, w01 = wx * omy, w10 = omx * wy, w11 = wx * wy;

    const uint32_t* a00 = (const uint32_t*)&u00;
    const uint32_t* a01 = (const uint32_t*)&u01;
    const uint32_t* a10 = (const uint32_t*)&u10;
    const uint32_t* a11 = (const uint32_t*)&u11;

    uint32_t hw[4], lw[4];
#pragma unroll
    for (int t = 0; t < 4; t++) {
        float2 f00 = __half22float2(*(const __half2*)&a00[t]);
        float2 f01 = __half22float2(*(const __half2*)&a01[t]);
        float2 f10 = __half22float2(*(const __half2*)&a10[t]);
        float2 f11 = __half22float2(*(const __half2*)&a11[t]);
        float r0 = f00.x * w00 + f01.x * w01 + f10.x * w10 + f11.x * w11;
        float r1 = f00.y * w00 + f01.y * w01 + f10.y * w10 + f11.y * w11;
        __nv_bfloat162 h2 = __floats2bfloat162_rn(r0, r1);
        float l0 = r0 - __bfloat162float(h2.x);
        float l1 = r1 - __bfloat162float(h2.y);
        __nv_bfloat162 l2 = __floats2bfloat162_rn(l0, l1);
        hw[t] = reinterpret_cast<uint32_t&>(h2);
        lw[t] = reinterpret_cast<uint32_t&>(l2);
    }
    size_t o = (size_t)v * CC + lane * 8;
    *(uint4*)(OAh + o) = make_uint4(hw[0], hw[1], hw[2], hw[3]);
    *(uint4*)(OAl + o) = make_uint4(lw[0], lw[1], lw[2], lw[3]);
}

// ---------------------------------------------------------------------------
// K3: weight prep -> Wt[n*K+k] = W[k*Nd+n] as bf16 hi/lo
// ---------------------------------------------------------------------------
__global__ void prep_weights(const float* __restrict__ W1, const float* __restrict__ W2,
                             const float* __restrict__ Wp) {
    int idx = blockIdx.x * 256 + threadIdx.x;
    int w = blockIdx.y;
    const float* W = (w == 0) ? W1 : (w == 1) ? W2 : Wp;
    int n = idx >> 8, k = idx & 255;
    float v = W[k * DD + n];
    __nv_bfloat16 hi = __float2bfloat16(v);
    float lo = v - __bfloat162float(hi);
    g_Whi[w][n * CC + k] = hi;
    g_Wlo[w][n * CC + k] = __float2bfloat16(lo);
}

// ---------------------------------------------------------------------------
// K4/5/6: HMMA bf16 GEMM, 3-term hi/lo split, SW128-swizzled packed rows.
//   All 12 ldsm.x4 issued up-front per k-step; 48 back-to-back MMAs follow.
// MODE 0: relu -> bf16 split   MODE 1: +pos_enc -> bf16 split   MODE 2: fp32 out
// ---------------------------------------------------------------------------
#define GBK 32
#define STAGEB 32768            // A 16 KB + B 16 KB
#define GSMEM (3 * STAGEB)      // 98304

__device__ __forceinline__ void split_store(__nv_bfloat16* Oh, __nv_bfloat16* Ol,
                                            size_t off, float a, float b) {
    __nv_bfloat162 h = __floats2bfloat162_rn(a, b);
    float la = a - __bfloat162float(h.x);
    float lb = b - __bfloat162float(h.y);
    __nv_bfloat162 l = __floats2bfloat162_rn(la, lb);
    *(__nv_bfloat162*)(Oh + off) = h;
    *(__nv_bfloat162*)(Ol + off) = l;
}

template <int MODE>
__global__ void __launch_bounds__(256, 2)
hmma_gemm(const __nv_bfloat16* __restrict__ Ah, const __nv_bfloat16* __restrict__ Al,
          const __nv_bfloat16* __restrict__ Bh, const __nv_bfloat16* __restrict__ Bl,
          const float* __restrict__ bias, float* __restrict__ OutF,
          __nv_bfloat16* __restrict__ OAh, __nv_bfloat16* __restrict__ OAl,
          const float* __restrict__ verts, const int* __restrict__ imgp) {
    extern __shared__ char smem[];
    const uint32_t sb = smem_u32(smem);
    const int tid = threadIdx.x;
    const int brow = blockIdx.x * 128;
    const int bcol = blockIdx.y * 128;
    const int warp = tid >> 5, lane = tid & 31;
    const int wm = warp >> 2, wn = warp & 3;  // 2 x 4 warps -> 64x32 warp tiles

    float acc[4][4][4];
#pragma unroll
    for (int i = 0; i < 4; i++)
#pragma unroll
        for (int j = 0; j < 4; j++)
#pragma unroll
            for (int q = 0; q < 4; q++) acc[i][j][q] = 0.0f;

    // ---- stage loader: rows swizzled SW128; row = [hi 64B | lo 64B] ----
    const int ldr = tid >> 3;        // 0..31 (row within 128 via +i*32)
    const int ldc = tid & 7;         // chunk 0..7
    auto load_stage = [&](int s, int chunk) {
        uint32_t dst = sb + s * STAGEB;
        const __nv_bfloat16* ga = (ldc < 4) ? Ah : Al;
        const __nv_bfloat16* gb = (ldc < 4) ? Bh : Bl;
        uint32_t cofs = ((uint32_t)chunk << 5) + ((ldc & 3) << 3);
#pragma unroll
        for (int i = 0; i < 4; i++) {
            int row = ldr + i * 32;
            uint32_t sw = (uint32_t)(row << 7) + (((uint32_t)(ldc ^ (row & 7))) << 4);
            cpa16(dst + sw, ga + (size_t)(brow + row) * CC + cofs);
            cpa16(dst + 16384 + sw, gb + (size_t)(bcol + row) * CC + cofs);
        }
    };

    // ---- precomputed ldsm bases (swizzle folded per-lane) ----
    uint32_t aBase[4], bBase[2];
#pragma unroll
    for (int mt = 0; mt < 4; mt++) {
        int row = wm * 64 + mt * 16 + (lane & 15);
        aBase[mt] = (uint32_t)(row << 7) + ((uint32_t)(((row & 7) ^ (lane >> 4))) << 4);
    }
#pragma unroll
    for (int nt2 = 0; nt2 < 2; nt2++) {
        int row = wn * 32 + nt2 * 16 + (lane & 7) + ((lane >> 4) << 3);
        bBase[nt2] = 16384u + (uint32_t)(row << 7) +
                     ((uint32_t)(((row & 7) ^ ((lane >> 3) & 1))) << 4);
    }

    load_stage(0, 0);
    CP_COMMIT();
    load_stage(1, 1);
    CP_COMMIT();

    for (int c = 0; c < 8; c++) {
        CP_WAIT1();
        __syncthreads();
        if (c + 2 < 8) load_stage((c + 2) % 3, c + 2);
        CP_COMMIT();

        const uint32_t st = sb + (c % 3) * STAGEB;
#pragma unroll
        for (int ks = 0; ks < 2; ks++) {
            const uint32_t kx = (uint32_t)(ks << 5);
            uint32_t bh[4][2], bl[4][2], af[4][4], al[4][4];
            // all fragment loads up-front (12 x ldsm.x4)
#pragma unroll
            for (int nt2 = 0; nt2 < 2; nt2++) {
                uint32_t a = (st + bBase[nt2]) ^ kx;
                ldsm4(a, bh[2 * nt2][0], bh[2 * nt2][1],
                      bh[2 * nt2 + 1][0], bh[2 * nt2 + 1][1]);
                ldsm4(a ^ 64u, bl[2 * nt2][0], bl[2 * nt2][1],
                      bl[2 * nt2 + 1][0], bl[2 * nt2 + 1][1]);
            }
#pragma unroll
            for (int mt = 0; mt < 4; mt++) {
                uint32_t a = (st + aBase[mt]) ^ kx;
                ldsm4(a, af[mt][0], af[mt][1], af[mt][2], af[mt][3]);
            }
#pragma unroll
            for (int mt = 0; mt < 4; mt++) {
                uint32_t a = ((st + aBase[mt]) ^ kx) ^ 64u;
                ldsm4(a, al[mt][0], al[mt][1], al[mt][2], al[mt][3]);
            }
            // 48 back-to-back MMAs: hi*hi, hi*lo, lo*hi
#pragma unroll
            for (int mt = 0; mt < 4; mt++)
#pragma unroll
                for (int nt = 0; nt < 4; nt++) mma16816(acc[mt][nt], af[mt], bh[nt]);
#pragma unroll
            for (int mt = 0; mt < 4; mt++)
#pragma unroll
                for (int nt = 0; nt < 4; nt++) mma16816(acc[mt][nt], af[mt], bl[nt]);
#pragma unroll
            for (int mt = 0; mt < 4; mt++)
#pragma unroll
                for (int nt = 0; nt < 4; nt++) mma16816(acc[mt][nt], al[mt], bh[nt]);
        }
    }

    // ---- epilogue (register-resident accumulators) ----
    const int rbase = brow + wm * 64 + (lane >> 2);
    const int cbase = bcol + wn * 32 + (lane & 3) * 2;
    float img = 1.0f;
    int coff = 0;
    if (MODE == 1) {
        img = read_img(imgp);
        coff = bcol >> 7;  // cols 0-127 <- x, 128-255 <- y
    }
#pragma unroll
    for (int mt = 0; mt < 4; mt++) {
        int r0 = rbase + mt * 16;
        int r1 = r0 + 8;
        float x0 = 0.0f, x1 = 0.0f;
        if (MODE == 1) {
            x0 = (verts[2 * r0 + coff] / img) * 1000.0f;
            x1 = (verts[2 * r1 + coff] / img) * 1000.0f;
        }
#pragma unroll
        for (int nt = 0; nt < 4; nt++) {
            int col = cbase + nt * 8;
            float b0 = __ldg(&bias[col]), b1 = __ldg(&bias[col + 1]);
            float v00 = acc[mt][nt][0] + b0, v01 = acc[mt][nt][1] + b1;
            float v10 = acc[mt][nt][2] + b0, v11 = acc[mt][nt][3] + b1;
            if (MODE == 0) {
                v00 = fmaxf(v00, 0.0f); v01 = fmaxf(v01, 0.0f);
                v10 = fmaxf(v10, 0.0f); v11 = fmaxf(v11, 0.0f);
            }
            if (MODE == 1) {
                int f = (col & 127) >> 1;
                float fr = exp2f(-(float)f * 0.20762050593046015f);  // 10000^(-f/64)
                float a0 = x0 * fr, a1 = x1 * fr;
                float k0 = rintf(a0 * 0.15915494309189535f);
                float q0 = fmaf(-k0, 6.2831854820251465f, a0);
                q0 = fmaf(-k0, -1.7484555e-07f, q0);
                float k1 = rintf(a1 * 0.15915494309189535f);
                float q1 = fmaf(-k1, 6.2831854820251465f, a1);
                q1 = fmaf(-k1, -1.7484555e-07f, q1);
                v00 += __sinf(q0); v01 += __cosf(q0);
                v10 += __sinf(q1); v11 += __cosf(q1);
            }
            if (MODE == 2) {
                *(float2*)(OutF + (size_t)r0 * DD + col) = make_float2(v00, v01);
                *(float2*)(OutF + (size_t)r1 * DD + col) = make_float2(v10, v11);
            } else {
                split_store(OAh, OAl, (size_t)r0 * DD + col, v00, v01);
                split_store(OAh, OAl, (size_t)r1 * DD + col, v10, v11);
            }
        }
    }
}

// ---------------------------------------------------------------------------
extern "C" void kernel_launch(void* const* d_in, const int* in_sizes, int n_in,
                              void* d_out, int out_size) {
    const float* features = (const float*)d_in[0];
    const float* vertices = (const float*)d_in[1];
    const int* imgp = (const int*)d_in[2];
    const float* W1 = (const float*)d_in[3];
    const float* b1 = (const float*)d_in[4];
    const float* W2 = (const float*)d_in[5];
    const float* b2 = (const float*)d_in[6];
    const float* Wp = (const float*)d_in[7];
    const float* bp = (const float*)d_in[8];
    float* out = (float*)d_out;

    void *pAh, *pAl, *pCh, *pCl, *pWh, *pWl;
    cudaGetSymbolAddress(&pAh, g_Ahi);
    cudaGetSymbolAddress(&pAl, g_Alo);
    cudaGetSymbolAddress(&pCh, g_Chi);
    cudaGetSymbolAddress(&pCl, g_Clo);
    cudaGetSymbolAddress(&pWh, g_Whi);
    cudaGetSymbolAddress(&pWl, g_Wlo);
    __nv_bfloat16* Ahi = (__nv_bfloat16*)pAh;
    __nv_bfloat16* Alo = (__nv_bfloat16*)pAl;
    __nv_bfloat16* Chi = (__nv_bfloat16*)pCh;
    __nv_bfloat16* Clo = (__nv_bfloat16*)pCl;
    __nv_bfloat16* Whi = (__nv_bfloat16*)pWh;
    __nv_bfloat16* Wlo = (__nv_bfloat16*)pWl;

    cudaFuncSetAttribute(hmma_gemm<0>, cudaFuncAttributeMaxDynamicSharedMemorySize, GSMEM);
    cudaFuncSetAttribute(hmma_gemm<1>, cudaFuncAttributeMaxDynamicSharedMemorySize, GSMEM);
    cudaFuncSetAttribute(hmma_gemm<2>, cudaFuncAttributeMaxDynamicSharedMemorySize, GSMEM);

    prep_weights<<<dim3(DD * CC / 256, 3), 256>>>(W1, W2, Wp);
    transpose_kernel<<<dim3(HWSZ / 64, CC / 64, BB), 256>>>(features);
    gather_kernel<<<MROWS / 4, 128>>>(vertices, imgp, Ahi, Alo);

    dim3 gg(MROWS / 128, DD / 128);
    // GEMM1: sampled @ W1 + b1, relu  (ping -> pong)
    hmma_gemm<0><<<gg, 256, GSMEM>>>(Ahi, Alo, Whi + 0 * (size_t)DD * CC,
                                     Wlo + 0 * (size_t)DD * CC, b1, nullptr,
                                     Chi, Clo, vertices, imgp);
    // GEMM2: h @ W2 + b2 + pos_enc   (pong -> ping)
    hmma_gemm<1><<<gg, 256, GSMEM>>>(Chi, Clo, Whi + 1 * (size_t)DD * CC,
                                     Wlo + 1 * (size_t)DD * CC, b2, nullptr,
                                     Ahi, Alo, vertices, imgp);
    // GEMM3: (vfeat+pos) @ Wp + bp -> fp32 out
    hmma_gemm<2><<<gg, 256, GSMEM>>>(Ahi, Alo, Whi + 2 * (size_t)DD * CC,
                                     Wlo + 2 * (size_t)DD * CC, bp, out,
                                     nullptr, nullptr, vertices, imgp);
}